// round 1
// baseline (speedup 1.0000x reference)
#include <cuda_runtime.h>
#include <cuda_bf16.h>

#define D_MODEL 1024
#define D_HEAD  64
#define SEQ     4096
#define BATCH   4
#define NROWS   (BATCH*SEQ)

// Scratch for projected Q, K, V (device globals: no allocation allowed)
__device__ float g_Q[NROWS * D_HEAD];
__device__ float g_K[NROWS * D_HEAD];
__device__ float g_V[NROWS * D_HEAD];

typedef unsigned long long u64;

// ---- packed f32x2 helpers (double-rate fp32 on sm_103a) ----
__device__ __forceinline__ void ffma2(u64 &d, u64 a, u64 b) {
    asm("fma.rn.f32x2 %0, %1, %2, %0;" : "+l"(d) : "l"(a), "l"(b));
}
__device__ __forceinline__ void mul2(u64 &d, u64 a, u64 b) {
    asm("mul.rn.f32x2 %0, %1, %2;" : "=l"(d) : "l"(a), "l"(b));
}
__device__ __forceinline__ u64 pack2(float lo, float hi) {
    u64 r; asm("mov.b64 %0, {%1, %2};" : "=l"(r) : "f"(lo), "f"(hi)); return r;
}
__device__ __forceinline__ void unpack2(float &lo, float &hi, u64 v) {
    asm("mov.b64 {%0, %1}, %2;" : "=f"(lo), "=f"(hi) : "l"(v));
}
// 16B shared load as two packed f32x2 operands
__device__ __forceinline__ void lds_2x64(u64 &a, u64 &b, const float* p) {
    u64 sp = __cvta_generic_to_shared((void*)p);
    asm volatile("ld.shared.v2.u64 {%0, %1}, [%2];" : "=l"(a), "=l"(b) : "l"(sp));
}

// ============================================================================
// Kernel 1: fused QKV projection.  [NROWS,1024] x [1024,64] -> Q,K,V
// 512 blocks x 256 threads; each block does 32 rows, all 64 cols, 3 matrices.
// ============================================================================
#define PROWS 32
#define XPAD  36   // 36%4==0 keeps 16B alignment for v2.u64 loads

__global__ __launch_bounds__(256) void qkv_kernel(
    const float* __restrict__ x,
    const float* __restrict__ Wq, const float* __restrict__ bq,
    const float* __restrict__ Wk, const float* __restrict__ bk,
    const float* __restrict__ Wv, const float* __restrict__ bv)
{
    __shared__ __align__(16) float sXT[32][XPAD];   // [k][row] transposed
    __shared__ float2 sWqk[32][64];                 // (wq, wk) interleaved
    __shared__ float  sWv [32][64];

    const int tid  = threadIdx.x;
    const int col  = tid & 63;
    const int rg   = tid >> 6;      // 0..3, each owns 8 rows
    const int row0 = blockIdx.x * PROWS;

    u64 aq[4] = {0,0,0,0}, ak[4] = {0,0,0,0}, av[4] = {0,0,0,0};

    for (int k0 = 0; k0 < D_MODEL; k0 += 32) {
        __syncthreads();
        // x tile (transposed into smem so row pairs are contiguous)
        #pragma unroll
        for (int i = tid; i < 32*32; i += 256) {
            int r = i >> 5, c = i & 31;
            sXT[c][r] = x[(size_t)(row0 + r) * D_MODEL + k0 + c];
        }
        // weight tiles
        #pragma unroll
        for (int i = tid; i < 32*64; i += 256) {
            int kk = i >> 6, c = i & 63;
            sWqk[kk][c] = make_float2(Wq[(k0+kk)*D_HEAD + c], Wk[(k0+kk)*D_HEAD + c]);
            sWv [kk][c] = Wv[(k0+kk)*D_HEAD + c];
        }
        __syncthreads();

        #pragma unroll 4
        for (int kk = 0; kk < 32; kk++) {
            float2 wqk = sWqk[kk][col];
            float  wv  = sWv [kk][col];
            u64 wq2 = pack2(wqk.x, wqk.x);
            u64 wk2 = pack2(wqk.y, wqk.y);
            u64 wv2 = pack2(wv,    wv);
            u64 xa, xb, xc, xd;
            lds_2x64(xa, xb, &sXT[kk][rg*8 + 0]);
            lds_2x64(xc, xd, &sXT[kk][rg*8 + 4]);
            ffma2(aq[0], wq2, xa); ffma2(aq[1], wq2, xb);
            ffma2(aq[2], wq2, xc); ffma2(aq[3], wq2, xd);
            ffma2(ak[0], wk2, xa); ffma2(ak[1], wk2, xb);
            ffma2(ak[2], wk2, xc); ffma2(ak[3], wk2, xd);
            ffma2(av[0], wv2, xa); ffma2(av[1], wv2, xb);
            ffma2(av[2], wv2, xc); ffma2(av[3], wv2, xd);
        }
    }

    const float bqv = bq[col], bkv = bk[col], bvv = bv[col];
    #pragma unroll
    for (int t = 0; t < 4; t++) {
        float lo, hi;
        int r = row0 + rg*8 + 2*t;
        unpack2(lo, hi, aq[t]);
        g_Q[(size_t)r*D_HEAD + col]     = lo + bqv;
        g_Q[(size_t)(r+1)*D_HEAD + col] = hi + bqv;
        unpack2(lo, hi, ak[t]);
        g_K[(size_t)r*D_HEAD + col]     = lo + bkv;
        g_K[(size_t)(r+1)*D_HEAD + col] = hi + bkv;
        unpack2(lo, hi, av[t]);
        g_V[(size_t)r*D_HEAD + col]     = lo + bvv;
        g_V[(size_t)(r+1)*D_HEAD + col] = hi + bvv;
    }
}

// ============================================================================
// Kernel 2: flash attention. grid (64 q-tiles, 4 batches) x 256 threads.
// Each thread owns one query row q = tid>>2 shared with 3 peers (sub = tid&3):
//   scores for keys k = sub + 4*j (j=0..15), output dims h = sub*16 .. +15.
// ============================================================================
#define PAD 68   // 68%4==0 (16B alignment), 68%32==4 (conflict-free rows)

__global__ __launch_bounds__(256, 2) void attn_kernel(float* __restrict__ out)
{
    extern __shared__ __align__(16) float sm[];
    float* sQ = sm;
    float* sK = sm + 64*PAD;
    float* sV = sm + 2*64*PAD;
    float* sP = sm + 3*64*PAD;

    const int b    = blockIdx.y;
    const int q0   = blockIdx.x * 64;
    const int base = b * SEQ;
    const int tid  = threadIdx.x;
    const int q    = tid >> 2;
    const int sub  = tid & 3;
    const float scale = 0.125f;   // 1/sqrt(64)

    for (int i = tid; i < 64*64; i += 256) {
        int r = i >> 6, c = i & 63;
        sQ[r*PAD + c] = g_Q[(size_t)(base + q0 + r)*D_HEAD + c];
    }

    u64 O2[8] = {0,0,0,0,0,0,0,0};
    float m = -1e30f, l = 0.f;

    for (int kt = 0; kt < SEQ/64; kt++) {
        __syncthreads();   // prev-iter PV reads done before overwriting tiles
        const int krow = base + kt*64;
        for (int i = tid; i < 64*64; i += 256) {
            int r = i >> 6, c = i & 63;
            sK[r*PAD + c] = g_K[(size_t)(krow + r)*D_HEAD + c];
            sV[r*PAD + c] = g_V[(size_t)(krow + r)*D_HEAD + c];
        }
        __syncthreads();

        // ---- S = Q . K^T (16 keys per thread), packed over head-dim pairs ----
        u64 acc[16];
        #pragma unroll
        for (int j = 0; j < 16; j++) acc[j] = 0;
        #pragma unroll 2
        for (int h0 = 0; h0 < 64; h0 += 4) {
            u64 qa, qb; lds_2x64(qa, qb, &sQ[q*PAD + h0]);
            #pragma unroll
            for (int j = 0; j < 16; j++) {
                u64 ka, kb; lds_2x64(ka, kb, &sK[(sub + 4*j)*PAD + h0]);
                ffma2(acc[j], qa, ka);
                ffma2(acc[j], qb, kb);
            }
        }
        float s[16];
        float mt = -1e30f;
        #pragma unroll
        for (int j = 0; j < 16; j++) {
            float lo, hi; unpack2(lo, hi, acc[j]);
            s[j] = (lo + hi) * scale;
            mt = fmaxf(mt, s[j]);
        }
        // group-of-4 max (lanes q*4+sub are adjacent)
        mt = fmaxf(mt, __shfl_xor_sync(0xffffffffu, mt, 1));
        mt = fmaxf(mt, __shfl_xor_sync(0xffffffffu, mt, 2));
        const float m_new = fmaxf(m, mt);
        const float corr  = __expf(m - m_new);
        float lsum = 0.f;
        #pragma unroll
        for (int j = 0; j < 16; j++) {
            float p = __expf(s[j] - m_new);
            lsum += p;
            sP[q*PAD + sub + 4*j] = p;
        }
        l = l * corr + lsum;   // per-thread partial; summed across group at end
        m = m_new;
        u64 c2 = pack2(corr, corr);
        #pragma unroll
        for (int t = 0; t < 8; t++) mul2(O2[t], O2[t], c2);

        __syncthreads();       // sP fully written before PV reads

        // ---- O += P . V  (16 head dims per thread, packed pairs) ----
        #pragma unroll 4
        for (int k = 0; k < 64; k++) {
            float p = sP[q*PAD + k];
            u64 p2 = pack2(p, p);
            #pragma unroll
            for (int u = 0; u < 4; u++) {
                u64 va, vb; lds_2x64(va, vb, &sV[k*PAD + sub*16 + 4*u]);
                ffma2(O2[2*u],   p2, va);
                ffma2(O2[2*u+1], p2, vb);
            }
        }
    }

    // final normalization: sum l across the 4-thread group
    l += __shfl_xor_sync(0xffffffffu, l, 1);
    l += __shfl_xor_sync(0xffffffffu, l, 2);
    const float inv = 1.0f / l;

    float* orow = out + (size_t)(base + q0 + q)*D_HEAD + sub*16;
    #pragma unroll
    for (int u = 0; u < 4; u++) {
        float a0, a1, a2, a3;
        unpack2(a0, a1, O2[2*u]);
        unpack2(a2, a3, O2[2*u+1]);
        float4 v4 = make_float4(a0*inv, a1*inv, a2*inv, a3*inv);
        *reinterpret_cast<float4*>(orow + 4*u) = v4;
    }
}

// ============================================================================
extern "C" void kernel_launch(void* const* d_in, const int* in_sizes, int n_in,
                              void* d_out, int out_size)
{
    const float* x  = (const float*)d_in[0];
    const float* Wq = (const float*)d_in[1];
    const float* bq = (const float*)d_in[2];
    const float* Wk = (const float*)d_in[3];
    const float* bk = (const float*)d_in[4];
    const float* Wv = (const float*)d_in[5];
    const float* bv = (const float*)d_in[6];
    float* out = (float*)d_out;

    qkv_kernel<<<NROWS / PROWS, 256>>>(x, Wq, bq, Wk, bk, Wv, bv);

    const int smem = 4 * 64 * PAD * (int)sizeof(float);   // 69632 B
    cudaFuncSetAttribute(attn_kernel,
                         cudaFuncAttributeMaxDynamicSharedMemorySize, smem);
    attn_kernel<<<dim3(SEQ/64, BATCH), 256, smem>>>(out);
}

// round 2
// speedup vs baseline: 2.8163x; 2.8163x over previous
#include <cuda_runtime.h>
#include <cuda_bf16.h>

#define D_MODEL 1024
#define D_HEAD  64
#define SEQ     4096
#define BATCH   4
#define NROWS   (BATCH*SEQ)

// Scratch for projected Q, K, V (device globals: no allocation allowed)
__device__ float g_Q[NROWS * D_HEAD];
__device__ float g_K[NROWS * D_HEAD];
__device__ float g_V[NROWS * D_HEAD];

typedef unsigned long long u64;

// ---- packed f32x2 helpers (double-rate fp32 on sm_103a) ----
__device__ __forceinline__ void ffma2(u64 &d, u64 a, u64 b) {
    asm("fma.rn.f32x2 %0, %1, %2, %0;" : "+l"(d) : "l"(a), "l"(b));
}
__device__ __forceinline__ void mul2(u64 &d, u64 a, u64 b) {
    asm("mul.rn.f32x2 %0, %1, %2;" : "=l"(d) : "l"(a), "l"(b));
}
__device__ __forceinline__ u64 pack2(float lo, float hi) {
    u64 r; asm("mov.b64 %0, {%1, %2};" : "=l"(r) : "f"(lo), "f"(hi)); return r;
}
__device__ __forceinline__ void unpack2(float &lo, float &hi, u64 v) {
    asm("mov.b64 {%0, %1}, %2;" : "=f"(lo), "=f"(hi) : "l"(v));
}
// 16B shared load as two packed f32x2 operands
__device__ __forceinline__ void lds_2x64(u64 &a, u64 &b, const float* p) {
    u64 sp = __cvta_generic_to_shared((void*)p);
    asm volatile("ld.shared.v2.u64 {%0, %1}, [%2];" : "=l"(a), "=l"(b) : "l"(sp));
}
__device__ __forceinline__ void sts64(float* p, u64 v) {
    u64 sp = __cvta_generic_to_shared((void*)p);
    asm volatile("st.shared.u64 [%0], %1;" :: "l"(sp), "l"(v));
}

// ============================================================================
// Kernel 1: fused QKV projection.  [NROWS,1024] x [1024,64] -> Q,K,V
// ============================================================================
#define PROWS 32
#define XPAD  36

__global__ __launch_bounds__(256) void qkv_kernel(
    const float* __restrict__ x,
    const float* __restrict__ Wq, const float* __restrict__ bq,
    const float* __restrict__ Wk, const float* __restrict__ bk,
    const float* __restrict__ Wv, const float* __restrict__ bv)
{
    __shared__ __align__(16) float sXT[32][XPAD];   // [k][row] transposed
    __shared__ float2 sWqk[32][64];
    __shared__ float  sWv [32][64];

    const int tid  = threadIdx.x;
    const int col  = tid & 63;
    const int rg   = tid >> 6;      // 0..3, each owns 8 rows
    const int row0 = blockIdx.x * PROWS;

    u64 aq[4] = {0,0,0,0}, ak[4] = {0,0,0,0}, av[4] = {0,0,0,0};

    for (int k0 = 0; k0 < D_MODEL; k0 += 32) {
        __syncthreads();
        #pragma unroll
        for (int i = tid; i < 32*32; i += 256) {
            int r = i >> 5, c = i & 31;
            sXT[c][r] = x[(size_t)(row0 + r) * D_MODEL + k0 + c];
        }
        #pragma unroll
        for (int i = tid; i < 32*64; i += 256) {
            int kk = i >> 6, c = i & 63;
            sWqk[kk][c] = make_float2(Wq[(k0+kk)*D_HEAD + c], Wk[(k0+kk)*D_HEAD + c]);
            sWv [kk][c] = Wv[(k0+kk)*D_HEAD + c];
        }
        __syncthreads();

        #pragma unroll 4
        for (int kk = 0; kk < 32; kk++) {
            float2 wqk = sWqk[kk][col];
            float  wv  = sWv [kk][col];
            u64 wq2 = pack2(wqk.x, wqk.x);
            u64 wk2 = pack2(wqk.y, wqk.y);
            u64 wv2 = pack2(wv,    wv);
            u64 xa, xb, xc, xd;
            lds_2x64(xa, xb, &sXT[kk][rg*8 + 0]);
            lds_2x64(xc, xd, &sXT[kk][rg*8 + 4]);
            ffma2(aq[0], wq2, xa); ffma2(aq[1], wq2, xb);
            ffma2(aq[2], wq2, xc); ffma2(aq[3], wq2, xd);
            ffma2(ak[0], wk2, xa); ffma2(ak[1], wk2, xb);
            ffma2(ak[2], wk2, xc); ffma2(ak[3], wk2, xd);
            ffma2(av[0], wv2, xa); ffma2(av[1], wv2, xb);
            ffma2(av[2], wv2, xc); ffma2(av[3], wv2, xd);
        }
    }

    const float bqv = bq[col], bkv = bk[col], bvv = bv[col];
    #pragma unroll
    for (int t = 0; t < 4; t++) {
        float lo, hi;
        int r = row0 + rg*8 + 2*t;
        unpack2(lo, hi, aq[t]);
        g_Q[(size_t)r*D_HEAD + col]     = lo + bqv;
        g_Q[(size_t)(r+1)*D_HEAD + col] = hi + bqv;
        unpack2(lo, hi, ak[t]);
        g_K[(size_t)r*D_HEAD + col]     = lo + bkv;
        g_K[(size_t)(r+1)*D_HEAD + col] = hi + bkv;
        unpack2(lo, hi, av[t]);
        g_V[(size_t)r*D_HEAD + col]     = lo + bvv;
        g_V[(size_t)(r+1)*D_HEAD + col] = hi + bvv;
    }
}

// ============================================================================
// Kernel 2: register-tiled flash attention.
// CTA: 128 q-rows x full seq. 256 threads = 16 (tq) x 16 (tk).
// Thread tile: QK = 8q x 4k (acc packed over q-pairs), PV = 8q x 4h.
// smem: sQT[h][q] (Q^T, pre-scaled), sKT[h][k] (K^T), sV[k][h], sPT[k][q].
// ============================================================================
#define QTILE 128
#define QPAD  132    // 128 + 4, %4==0 for 16B-aligned q-pair vectors
#define KPAD  68     // 64 + 4

__global__ __launch_bounds__(256, 1) void attn_kernel(float* __restrict__ out)
{
    extern __shared__ __align__(16) float sm[];
    float* sQT = sm;                      // 64 * QPAD
    float* sKT = sQT + 64*QPAD;           // 64 * KPAD
    float* sV  = sKT + 64*KPAD;           // 64 * KPAD
    float* sPT = sV  + 64*KPAD;           // 64 * QPAD

    const int b    = blockIdx.y;
    const int q0   = blockIdx.x * QTILE;
    const int base = b * SEQ;
    const int tid  = threadIdx.x;
    const int tq   = tid >> 4;            // 0..15 -> q rows tq*8 .. +7
    const int tk   = tid & 15;            // 0..15 -> keys/h-dims tk*4 .. +3
    const int qr   = tq * 8;

    // load Q tile transposed, pre-scaled by 1/sqrt(64)
    for (int i = tid; i < QTILE*64; i += 256) {
        int r = i >> 6, c = i & 63;
        sQT[c*QPAD + r] = g_Q[(size_t)(base + q0 + r)*D_HEAD + c] * 0.125f;
    }

    u64 O2[4][4];                         // [q-pair][h] packed over q
    #pragma unroll
    for (int ip = 0; ip < 4; ip++)
        #pragma unroll
        for (int j = 0; j < 4; j++) O2[ip][j] = 0;

    float m[8], l[8];
    #pragma unroll
    for (int i = 0; i < 8; i++) { m[i] = -1e30f; l[i] = 0.f; }

    for (int kt = 0; kt < SEQ/64; kt++) {
        __syncthreads();   // prev-iter PV reads done
        const int krow = base + kt*64;
        for (int i = tid; i < 64*64; i += 256) {
            int r = i >> 6, c = i & 63;
            sKT[c*KPAD + r] = g_K[(size_t)(krow + r)*D_HEAD + c];
            sV [r*KPAD + c] = g_V[(size_t)(krow + r)*D_HEAD + c];
        }
        __syncthreads();

        // ---- S = Q.K^T : 8q x 4k per thread, packed over q-pairs ----
        u64 S2[4][4];
        #pragma unroll
        for (int ip = 0; ip < 4; ip++)
            #pragma unroll
            for (int j = 0; j < 4; j++) S2[ip][j] = 0;

        #pragma unroll 4
        for (int h = 0; h < 64; h++) {
            u64 qp[4];
            lds_2x64(qp[0], qp[1], &sQT[h*QPAD + qr]);
            lds_2x64(qp[2], qp[3], &sQT[h*QPAD + qr + 4]);
            u64 k01, k23;
            lds_2x64(k01, k23, &sKT[h*KPAD + tk*4]);
            float k0,k1,k2,k3;
            unpack2(k0, k1, k01); unpack2(k2, k3, k23);
            u64 kb[4] = { pack2(k0,k0), pack2(k1,k1), pack2(k2,k2), pack2(k3,k3) };
            #pragma unroll
            for (int ip = 0; ip < 4; ip++)
                #pragma unroll
                for (int j = 0; j < 4; j++)
                    ffma2(S2[ip][j], qp[ip], kb[j]);
        }

        // ---- online softmax ----
        float sv[8][4];
        #pragma unroll
        for (int ip = 0; ip < 4; ip++)
            #pragma unroll
            for (int j = 0; j < 4; j++)
                unpack2(sv[2*ip][j], sv[2*ip+1][j], S2[ip][j]);

        float corr[8];
        #pragma unroll
        for (int i = 0; i < 8; i++) {
            float mt = fmaxf(fmaxf(sv[i][0], sv[i][1]), fmaxf(sv[i][2], sv[i][3]));
            mt = fmaxf(mt, __shfl_xor_sync(0xffffffffu, mt, 1));
            mt = fmaxf(mt, __shfl_xor_sync(0xffffffffu, mt, 2));
            mt = fmaxf(mt, __shfl_xor_sync(0xffffffffu, mt, 4));
            mt = fmaxf(mt, __shfl_xor_sync(0xffffffffu, mt, 8));
            float mn = fmaxf(m[i], mt);
            corr[i] = __expf(m[i] - mn);
            m[i] = mn;
            float ls = 0.f;
            #pragma unroll
            for (int j = 0; j < 4; j++) {
                float p = __expf(sv[i][j] - mn);
                ls += p;
                sv[i][j] = p;
            }
            l[i] = l[i]*corr[i] + ls;   // partial over this thread's 4 keys
        }
        // write P^T as q-pairs
        #pragma unroll
        for (int j = 0; j < 4; j++)
            #pragma unroll
            for (int ip = 0; ip < 4; ip++)
                sts64(&sPT[(tk*4 + j)*QPAD + qr + 2*ip], pack2(sv[2*ip][j], sv[2*ip+1][j]));
        // rescale O
        #pragma unroll
        for (int ip = 0; ip < 4; ip++) {
            u64 c2 = pack2(corr[2*ip], corr[2*ip+1]);
            #pragma unroll
            for (int j = 0; j < 4; j++) mul2(O2[ip][j], O2[ip][j], c2);
        }
        __syncthreads();   // sPT visible

        // ---- O += P.V : 8q x 4h per thread ----
        #pragma unroll 4
        for (int k = 0; k < 64; k++) {
            u64 v01, v23;
            lds_2x64(v01, v23, &sV[k*KPAD + tk*4]);
            float v0,v1,v2,v3;
            unpack2(v0, v1, v01); unpack2(v2, v3, v23);
            u64 vb[4] = { pack2(v0,v0), pack2(v1,v1), pack2(v2,v2), pack2(v3,v3) };
            u64 pp[4];
            lds_2x64(pp[0], pp[1], &sPT[k*QPAD + qr]);
            lds_2x64(pp[2], pp[3], &sPT[k*QPAD + qr + 4]);
            #pragma unroll
            for (int ip = 0; ip < 4; ip++)
                #pragma unroll
                for (int j = 0; j < 4; j++)
                    ffma2(O2[ip][j], pp[ip], vb[j]);
        }
    }

    // final: reduce l across the 16 tk-lanes, normalize, store
    float inv[8];
    #pragma unroll
    for (int i = 0; i < 8; i++) {
        float li = l[i];
        li += __shfl_xor_sync(0xffffffffu, li, 1);
        li += __shfl_xor_sync(0xffffffffu, li, 2);
        li += __shfl_xor_sync(0xffffffffu, li, 4);
        li += __shfl_xor_sync(0xffffffffu, li, 8);
        inv[i] = 1.0f / li;
    }
    #pragma unroll
    for (int ip = 0; ip < 4; ip++) {
        const size_t r0 = (size_t)(base + q0 + qr + 2*ip) * D_HEAD + tk*4;
        #pragma unroll
        for (int j = 0; j < 4; j++) {
            float lo, hi;
            unpack2(lo, hi, O2[ip][j]);
            out[r0 + j]           = lo * inv[2*ip];
            out[r0 + D_HEAD + j]  = hi * inv[2*ip+1];
        }
    }
}

// ============================================================================
extern "C" void kernel_launch(void* const* d_in, const int* in_sizes, int n_in,
                              void* d_out, int out_size)
{
    const float* x  = (const float*)d_in[0];
    const float* Wq = (const float*)d_in[1];
    const float* bq = (const float*)d_in[2];
    const float* Wk = (const float*)d_in[3];
    const float* bk = (const float*)d_in[4];
    const float* Wv = (const float*)d_in[5];
    const float* bv = (const float*)d_in[6];
    float* out = (float*)d_out;

    qkv_kernel<<<NROWS / PROWS, 256>>>(x, Wq, bq, Wk, bk, Wv, bv);

    const int smem = (2*64*QPAD + 2*64*KPAD) * (int)sizeof(float);   // 102400 B
    cudaFuncSetAttribute(attn_kernel,
                         cudaFuncAttributeMaxDynamicSharedMemorySize, smem);
    attn_kernel<<<dim3(SEQ/QTILE, BATCH), 256, smem>>>(out);
}